// round 1
// baseline (speedup 1.0000x reference)
#include <cuda_runtime.h>
#include <math.h>

#define Bn 16
#define Qn 300
#define Dn 256
#define Hn 8
#define Pn 4
#define Fn 2048
#define HGn 100
#define WGn 100
#define HWn 10000
#define DHn 32
#define LN_EPS 1e-5f

#define BQ (Bn*Qn)            // 4800
#define MEMROWS (Bn*HWn)      // 160000

// ---------------- scratch (allocation-free: __device__ globals) ----------------
__device__ float g_qkv[BQ*3*Dn];          // 3.7M
__device__ float g_scores[Bn*Hn*Qn*Qn];   // 11.52M
__device__ float g_sa[BQ*Dn];
__device__ float g_x1[BQ*Dn];
__device__ float g_x2[BQ*Dn];
__device__ float g_tmp[BQ*Dn];
__device__ float g_ca[BQ*Dn];
__device__ float g_vals[MEMROWS*Dn];      // 41M floats (164 MB)
__device__ float g_ff[BQ*Fn];             // 9.8M

// ---------------- generic tiled SGEMM: C[M,N] = A[M,K] @ W[K,N] + bias (opt ReLU) ----
// requires M%64==0, N%64==0, K%16==0
#define BM 64
#define BN 64
#define BK 16

__global__ __launch_bounds__(256) void gemm_bias_kernel(
    const float* __restrict__ A, const float* __restrict__ W,
    const float* __restrict__ bias, float* __restrict__ C,
    int M, int N, int K, int relu)
{
    __shared__ float As[BK][BM];
    __shared__ float Bs[BK][BN];
    int tid = threadIdx.x;
    int tx = tid & 15, ty = tid >> 4;
    int bm = blockIdx.y * BM, bn = blockIdx.x * BN;

    float acc[4][4];
#pragma unroll
    for (int i = 0; i < 4; i++)
#pragma unroll
        for (int j = 0; j < 4; j++) acc[i][j] = 0.f;

    int a_row = tid >> 2;          // 0..63
    int a_col = (tid & 3) * 4;     // 0,4,8,12
    int b_row = tid >> 4;          // 0..15
    int b_col = (tid & 15) * 4;    // 0..60

    const float* Aptr = A + (size_t)(bm + a_row) * K + a_col;
    const float* Wptr = W + (size_t)b_row * N + bn + b_col;

    for (int kt = 0; kt < K; kt += BK) {
        float4 av = *(const float4*)(Aptr + kt);
        As[a_col + 0][a_row] = av.x;
        As[a_col + 1][a_row] = av.y;
        As[a_col + 2][a_row] = av.z;
        As[a_col + 3][a_row] = av.w;
        float4 bv = *(const float4*)(Wptr + (size_t)kt * N);
        *(float4*)&Bs[b_row][b_col] = bv;
        __syncthreads();
#pragma unroll
        for (int kk = 0; kk < BK; kk++) {
            float ar[4], br[4];
#pragma unroll
            for (int i = 0; i < 4; i++) ar[i] = As[kk][ty + 16 * i];
#pragma unroll
            for (int j = 0; j < 4; j++) br[j] = Bs[kk][tx + 16 * j];
#pragma unroll
            for (int i = 0; i < 4; i++)
#pragma unroll
                for (int j = 0; j < 4; j++) acc[i][j] += ar[i] * br[j];
        }
        __syncthreads();
    }

#pragma unroll
    for (int i = 0; i < 4; i++) {
        int row = bm + ty + 16 * i;
#pragma unroll
        for (int j = 0; j < 4; j++) {
            int col = bn + tx + 16 * j;
            float v = acc[i][j] + bias[col];
            if (relu) v = fmaxf(v, 0.f);
            C[(size_t)row * N + col] = v;
        }
    }
}

// ---------------- Q @ K^T scaled ----------------
__global__ void qk_kernel(const float* __restrict__ qkv, float* __restrict__ scores)
{
    int ki = blockIdx.x * 16 + threadIdx.x;
    int qi = blockIdx.y * 16 + threadIdx.y;
    int bh = blockIdx.z;
    if (ki >= Qn || qi >= Qn) return;
    int b = bh >> 3, h = bh & 7;
    const float* qp = qkv + (size_t)(b * Qn + qi) * (3 * Dn) + h * DHn;
    const float* kp = qkv + (size_t)(b * Qn + ki) * (3 * Dn) + Dn + h * DHn;
    float s = 0.f;
#pragma unroll
    for (int d = 0; d < DHn; d++) s += qp[d] * kp[d];
    scores[((size_t)bh * Qn + qi) * Qn + ki] = s * 0.17677669529663689f; // 1/sqrt(32)
}

// ---------------- row softmax over 300, in-place ----------------
__global__ void softmax_kernel(float* __restrict__ sc)
{
    int row = blockIdx.x;
    float* p = sc + (size_t)row * Qn;
    int t = threadIdx.x; // 128
    float v0 = p[t];
    float v1 = p[t + 128];
    float v2 = (t + 256 < Qn) ? p[t + 256] : -1e30f;
    float m = fmaxf(v0, fmaxf(v1, v2));
    __shared__ float red[4];
#pragma unroll
    for (int o = 16; o; o >>= 1) m = fmaxf(m, __shfl_xor_sync(~0u, m, o));
    if ((t & 31) == 0) red[t >> 5] = m;
    __syncthreads();
    m = fmaxf(fmaxf(red[0], red[1]), fmaxf(red[2], red[3]));
    float e0 = expf(v0 - m), e1 = expf(v1 - m);
    float e2 = (t + 256 < Qn) ? expf(v2 - m) : 0.f;
    float su = e0 + e1 + e2;
#pragma unroll
    for (int o = 16; o; o >>= 1) su += __shfl_xor_sync(~0u, su, o);
    __syncthreads();
    if ((t & 31) == 0) red[t >> 5] = su;
    __syncthreads();
    su = red[0] + red[1] + red[2] + red[3];
    float inv = 1.f / su;
    p[t] = e0 * inv;
    p[t + 128] = e1 * inv;
    if (t + 256 < Qn) p[t + 256] = e2 * inv;
}

// ---------------- attn @ V ----------------
__global__ __launch_bounds__(256) void av_kernel(
    const float* __restrict__ qkv, const float* __restrict__ attn, float* __restrict__ sa)
{
    __shared__ float Vs[Qn * DHn]; // 300*32*4 = 38.4 KB
    int b = blockIdx.x >> 3, h = blockIdx.x & 7;
    int tid = threadIdx.x;
    for (int i = tid; i < Qn * DHn; i += 256) {
        int k = i >> 5, d = i & 31;
        Vs[i] = qkv[(size_t)(b * Qn + k) * (3 * Dn) + 2 * Dn + h * DHn + d];
    }
    __syncthreads();
    int d = tid & 31, qs = tid >> 5;
    for (int q0 = qs; q0 < Qn; q0 += 8) {
        const float* ap = attn + ((size_t)blockIdx.x * Qn + q0) * Qn;
        float acc = 0.f;
        for (int k = 0; k < Qn; k++) acc += ap[k] * Vs[(k << 5) + d];
        sa[(size_t)(b * Qn + q0) * Dn + h * DHn + d] = acc;
    }
}

// ---------------- fused residual-add + LayerNorm ----------------
__global__ void add_ln_kernel(const float* __restrict__ a, const float* __restrict__ r,
                              const float* __restrict__ g, const float* __restrict__ be,
                              float* __restrict__ out)
{
    int row = blockIdx.x, t = threadIdx.x;
    size_t idx = (size_t)row * Dn + t;
    float v = a[idx] + r[idx];
    __shared__ float red[8];
    float s = v;
#pragma unroll
    for (int o = 16; o; o >>= 1) s += __shfl_xor_sync(~0u, s, o);
    if ((t & 31) == 0) red[t >> 5] = s;
    __syncthreads();
    float mean = 0.f;
#pragma unroll
    for (int i = 0; i < 8; i++) mean += red[i];
    mean *= (1.f / Dn);
    float d = v - mean;
    float s2 = d * d;
#pragma unroll
    for (int o = 16; o; o >>= 1) s2 += __shfl_xor_sync(~0u, s2, o);
    __syncthreads();
    if ((t & 31) == 0) red[t >> 5] = s2;
    __syncthreads();
    float var = 0.f;
#pragma unroll
    for (int i = 0; i < 8; i++) var += red[i];
    var *= (1.f / Dn);
    out[idx] = d * rsqrtf(var + LN_EPS) * g[t] + be[t];
}

// ---------------- fused ref/offs/attw matvecs + P-softmax + bilinear sampling ----------------
__global__ __launch_bounds__(256) void refsample_kernel(
    const float* __restrict__ x1,
    const float* __restrict__ ref_w, const float* __restrict__ ref_b,
    const float* __restrict__ off_w, const float* __restrict__ off_b,
    const float* __restrict__ attw_w, const float* __restrict__ attw_b,
    const float* __restrict__ vals, float* __restrict__ ca)
{
    __shared__ float xrow[Dn];
    __shared__ float sref[2];
    __shared__ float soffs[Hn * Pn * 2]; // 64
    __shared__ float alog[Hn * Pn];      // 32
    __shared__ float swts[Hn * Pn];      // 32

    int bq = blockIdx.x;
    int b = bq / Qn;
    int t = threadIdx.x;

    xrow[t] = x1[(size_t)bq * Dn + t];
    __syncthreads();

    if (t < 2) {
        float s = ref_b[t];
        for (int d = 0; d < Dn; d++) s += xrow[d] * ref_w[d * 2 + t];
        sref[t] = 1.f / (1.f + expf(-s));
    } else if (t < 66) {
        int j = t - 2;
        float s = off_b[j];
        for (int d = 0; d < Dn; d++) s += xrow[d] * off_w[d * 64 + j];
        soffs[j] = s;
    } else if (t < 98) {
        int j = t - 66;
        float s = attw_b[j];
        for (int d = 0; d < Dn; d++) s += xrow[d] * attw_w[d * 32 + j];
        alog[j] = s;
    }
    __syncthreads();

    if (t < Hn) {
        float m = alog[t * 4];
#pragma unroll
        for (int p = 1; p < 4; p++) m = fmaxf(m, alog[t * 4 + p]);
        float e[4], su = 0.f;
#pragma unroll
        for (int p = 0; p < 4; p++) { e[p] = expf(alog[t * 4 + p] - m); su += e[p]; }
        float inv = 1.f / su;
#pragma unroll
        for (int p = 0; p < 4; p++) swts[t * 4 + p] = e[p] * inv;
    }
    __syncthreads();

    int h = t >> 5, d = t & 31;
    float rx = sref[0], ry = sref[1];
    const float* vb = vals + (size_t)b * HWn * Dn + h * DHn + d;
    float acc = 0.f;
#pragma unroll
    for (int p = 0; p < Pn; p++) {
        float lx = fminf(fmaxf(rx + soffs[h * 8 + p * 2 + 0], 0.f), 1.f);
        float ly = fminf(fmaxf(ry + soffs[h * 8 + p * 2 + 1], 0.f), 1.f);
        float sx = lx * (float)(WGn - 1);
        float sy = ly * (float)(HGn - 1);
        float x0f = floorf(sx), y0f = floorf(sy);
        int x0 = min(max((int)x0f, 0), WGn - 1);
        int y0 = min(max((int)y0f, 0), HGn - 1);
        int x1i = min(x0 + 1, WGn - 1);
        int y1i = min(y0 + 1, HGn - 1);
        float wx1 = sx - x0f, wx0 = 1.f - wx1;
        float wy1 = sy - y0f, wy0 = 1.f - wy1;
        float v00 = vb[(size_t)(y0 * WGn + x0) * Dn];
        float v01 = vb[(size_t)(y1i * WGn + x0) * Dn];
        float v10 = vb[(size_t)(y0 * WGn + x1i) * Dn];
        float v11 = vb[(size_t)(y1i * WGn + x1i) * Dn];
        float bil = v00 * wx0 * wy0 + v01 * wx0 * wy1 + v10 * wx1 * wy0 + v11 * wx1 * wy1;
        acc += swts[h * 4 + p] * bil;
    }
    ca[(size_t)bq * Dn + t] = acc;
}

// ---------------- launch ----------------
extern "C" void kernel_launch(void* const* d_in, const int* in_sizes, int n_in,
                              void* d_out, int out_size)
{
    const float* tgt        = (const float*)d_in[0];
    const float* memory     = (const float*)d_in[1];
    const float* in_proj_w  = (const float*)d_in[2];
    const float* in_proj_b  = (const float*)d_in[3];
    const float* out_proj_w = (const float*)d_in[4];
    const float* out_proj_b = (const float*)d_in[5];
    const float* norm1_g    = (const float*)d_in[6];
    const float* norm1_b    = (const float*)d_in[7];
    const float* ref_w      = (const float*)d_in[8];
    const float* ref_b      = (const float*)d_in[9];
    const float* off_w      = (const float*)d_in[10];
    const float* off_b      = (const float*)d_in[11];
    const float* attw_w     = (const float*)d_in[12];
    const float* attw_b     = (const float*)d_in[13];
    const float* vproj_w    = (const float*)d_in[14];
    const float* vproj_b    = (const float*)d_in[15];
    const float* oproj_w    = (const float*)d_in[16];
    const float* oproj_b    = (const float*)d_in[17];
    const float* norm2_g    = (const float*)d_in[18];
    const float* norm2_b    = (const float*)d_in[19];
    const float* lin1_w     = (const float*)d_in[20];
    const float* lin1_b     = (const float*)d_in[21];
    const float* lin2_w     = (const float*)d_in[22];
    const float* lin2_b     = (const float*)d_in[23];
    const float* norm3_g    = (const float*)d_in[24];
    const float* norm3_b    = (const float*)d_in[25];
    float* out = (float*)d_out;

    float *qkv, *scores, *sa, *x1, *x2, *tmp, *ca, *vals, *ff;
    cudaGetSymbolAddress((void**)&qkv,    g_qkv);
    cudaGetSymbolAddress((void**)&scores, g_scores);
    cudaGetSymbolAddress((void**)&sa,     g_sa);
    cudaGetSymbolAddress((void**)&x1,     g_x1);
    cudaGetSymbolAddress((void**)&x2,     g_x2);
    cudaGetSymbolAddress((void**)&tmp,    g_tmp);
    cudaGetSymbolAddress((void**)&ca,     g_ca);
    cudaGetSymbolAddress((void**)&vals,   g_vals);
    cudaGetSymbolAddress((void**)&ff,     g_ff);

    // 1. qkv projection [4800,256]@[256,768]
    gemm_bias_kernel<<<dim3(768 / BN, BQ / BM), 256>>>(tgt, in_proj_w, in_proj_b, qkv, BQ, 768, Dn, 0);
    // 2. value projection of memory [160000,256]@[256,256]
    gemm_bias_kernel<<<dim3(Dn / BN, MEMROWS / BM), 256>>>(memory, vproj_w, vproj_b, vals, MEMROWS, Dn, Dn, 0);
    // 3. scores
    qk_kernel<<<dim3((Qn + 15) / 16, (Qn + 15) / 16, Bn * Hn), dim3(16, 16)>>>(qkv, scores);
    // 4. softmax
    softmax_kernel<<<Bn * Hn * Qn, 128>>>(scores);
    // 5. attn @ V
    av_kernel<<<Bn * Hn, 256>>>(qkv, scores, sa);
    // 6. out_proj
    gemm_bias_kernel<<<dim3(Dn / BN, BQ / BM), 256>>>(sa, out_proj_w, out_proj_b, tmp, BQ, Dn, Dn, 0);
    // 7. x1 = LN(tgt + sa_out)
    add_ln_kernel<<<BQ, Dn>>>(tgt, tmp, norm1_g, norm1_b, x1);
    // 8. ref/offsets/weights + sampling -> ca (pre oproj)
    refsample_kernel<<<BQ, Dn>>>(x1, ref_w, ref_b, off_w, off_b, attw_w, attw_b, vals, ca);
    // 9. oproj
    gemm_bias_kernel<<<dim3(Dn / BN, BQ / BM), 256>>>(ca, oproj_w, oproj_b, tmp, BQ, Dn, Dn, 0);
    // 10. x2 = LN(x1 + ca_out)
    add_ln_kernel<<<BQ, Dn>>>(x1, tmp, norm2_g, norm2_b, x2);
    // 11. FFN lin1 + ReLU
    gemm_bias_kernel<<<dim3(Fn / BN, BQ / BM), 256>>>(x2, lin1_w, lin1_b, ff, BQ, Fn, Dn, 1);
    // 12. FFN lin2
    gemm_bias_kernel<<<dim3(Dn / BN, BQ / BM), 256>>>(ff, lin2_w, lin2_b, tmp, BQ, Dn, Fn, 0);
    // 13. out = LN(x2 + ffn)
    add_ln_kernel<<<BQ, Dn>>>(x2, tmp, norm3_g, norm3_b, out);
}

// round 2
// speedup vs baseline: 1.4765x; 1.4765x over previous
#include <cuda_runtime.h>
#include <math.h>
#include <stdint.h>

#define Bn 16
#define Qn 300
#define Dn 256
#define Hn 8
#define Pn 4
#define Fn 2048
#define HGn 100
#define WGn 100
#define HWn 10000
#define DHn 32
#define LN_EPS 1e-5f

#define BQ (Bn*Qn)            // 4800
#define MEMROWS (Bn*HWn)      // 160000

// ---------------- scratch (allocation-free: __device__ globals) ----------------
__device__ float g_qkv[BQ*3*Dn];
__device__ float g_scores[Bn*Hn*Qn*Qn];
__device__ float g_sa[BQ*Dn];
__device__ float g_x1[BQ*Dn];
__device__ float g_x2[BQ*Dn];
__device__ float g_tmp[BQ*Dn];
__device__ float g_ca[BQ*Dn];
__device__ float g_vals[MEMROWS*Dn];
__device__ float g_ff[BQ*Fn];

// ---------------- tf32 tensor-core GEMM ----------------
// C[M,N] = A[M,K] @ W[K,N] + bias, optional ReLU.
// Block tile 64(M) x 128(N), BK=16, 8 warps (2x4), warp tile 32x32,
// mma.sync.m16n8k8 tf32, double-buffered smem.
#define TBM 64
#define TBN 128
#define TBK 16

__device__ __forceinline__ float ftf32(float x) {
    float y;
    asm("cvt.rna.tf32.f32 %0, %1;" : "=f"(y) : "f"(x));
    return y;
}

__global__ __launch_bounds__(256) void gemm_tf32_kernel(
    const float* __restrict__ A, const float* __restrict__ W,
    const float* __restrict__ bias, float* __restrict__ C,
    int M, int N, int K, int relu)
{
    __shared__ float As[2][TBK][TBM + 4];
    __shared__ float Bs[2][TBK][TBN + 4];

    const int tid  = threadIdx.x;
    const int lane = tid & 31;
    const int warp = tid >> 5;
    const int wm = (warp >> 2) * 32;   // 0 or 32
    const int wn = (warp & 3) * 32;    // 0,32,64,96
    const int bm = blockIdx.y * TBM;
    const int bn = blockIdx.x * TBN;

    const int lq = lane >> 2;   // 0..7
    const int lr = lane & 3;    // 0..3

    // staging indices
    const int a_row = tid >> 2;          // 0..63
    const int a_col = (tid & 3) * 4;     // 0,4,8,12
    const int b_row = tid >> 4;          // 0..15
    const int b_col = (tid & 15) * 8;    // 0..120

    const float* Aptr = A + (size_t)(bm + a_row) * K + a_col;
    const float* Wptr = W + (size_t)b_row * N + bn + b_col;

    float c[2][4][4];
#pragma unroll
    for (int i = 0; i < 2; i++)
#pragma unroll
        for (int j = 0; j < 4; j++)
#pragma unroll
            for (int l = 0; l < 4; l++) c[i][j][l] = 0.f;

    // load chunk 0
    float4 av = *(const float4*)(Aptr);
    float4 bv0 = *(const float4*)(Wptr);
    float4 bv1 = *(const float4*)(Wptr + 4);
    {
        As[0][a_col + 0][a_row] = ftf32(av.x);
        As[0][a_col + 1][a_row] = ftf32(av.y);
        As[0][a_col + 2][a_row] = ftf32(av.z);
        As[0][a_col + 3][a_row] = ftf32(av.w);
        float4 t0 = make_float4(ftf32(bv0.x), ftf32(bv0.y), ftf32(bv0.z), ftf32(bv0.w));
        float4 t1 = make_float4(ftf32(bv1.x), ftf32(bv1.y), ftf32(bv1.z), ftf32(bv1.w));
        *(float4*)&Bs[0][b_row][b_col]     = t0;
        *(float4*)&Bs[0][b_row][b_col + 4] = t1;
    }
    __syncthreads();

    int buf = 0;
    for (int kt = 0; kt < K; kt += TBK) {
        const bool has_next = (kt + TBK) < K;
        if (has_next) {
            av  = *(const float4*)(Aptr + kt + TBK);
            bv0 = *(const float4*)(Wptr + (size_t)(kt + TBK) * N);
            bv1 = *(const float4*)(Wptr + (size_t)(kt + TBK) * N + 4);
        }

        // compute current buffer: two k8 steps
#pragma unroll
        for (int ks = 0; ks < TBK; ks += 8) {
            uint32_t a[2][4], b[4][2];
#pragma unroll
            for (int mt = 0; mt < 2; mt++) {
                int mr = wm + mt * 16 + lq;
                a[mt][0] = __float_as_uint(As[buf][ks + lr    ][mr]);
                a[mt][1] = __float_as_uint(As[buf][ks + lr    ][mr + 8]);
                a[mt][2] = __float_as_uint(As[buf][ks + lr + 4][mr]);
                a[mt][3] = __float_as_uint(As[buf][ks + lr + 4][mr + 8]);
            }
#pragma unroll
            for (int nt = 0; nt < 4; nt++) {
                int nc = wn + nt * 8 + lq;
                b[nt][0] = __float_as_uint(Bs[buf][ks + lr    ][nc]);
                b[nt][1] = __float_as_uint(Bs[buf][ks + lr + 4][nc]);
            }
#pragma unroll
            for (int mt = 0; mt < 2; mt++)
#pragma unroll
                for (int nt = 0; nt < 4; nt++) {
                    asm volatile(
                        "mma.sync.aligned.m16n8k8.row.col.f32.tf32.tf32.f32 "
                        "{%0,%1,%2,%3}, {%4,%5,%6,%7}, {%8,%9}, {%0,%1,%2,%3};"
                        : "+f"(c[mt][nt][0]), "+f"(c[mt][nt][1]),
                          "+f"(c[mt][nt][2]), "+f"(c[mt][nt][3])
                        : "r"(a[mt][0]), "r"(a[mt][1]), "r"(a[mt][2]), "r"(a[mt][3]),
                          "r"(b[nt][0]), "r"(b[nt][1]));
                }
        }

        if (has_next) {
            int nb = buf ^ 1;
            As[nb][a_col + 0][a_row] = ftf32(av.x);
            As[nb][a_col + 1][a_row] = ftf32(av.y);
            As[nb][a_col + 2][a_row] = ftf32(av.z);
            As[nb][a_col + 3][a_row] = ftf32(av.w);
            float4 t0 = make_float4(ftf32(bv0.x), ftf32(bv0.y), ftf32(bv0.z), ftf32(bv0.w));
            float4 t1 = make_float4(ftf32(bv1.x), ftf32(bv1.y), ftf32(bv1.z), ftf32(bv1.w));
            *(float4*)&Bs[nb][b_row][b_col]     = t0;
            *(float4*)&Bs[nb][b_row][b_col + 4] = t1;
        }
        __syncthreads();
        buf ^= 1;
    }

    // epilogue
#pragma unroll
    for (int mt = 0; mt < 2; mt++) {
#pragma unroll
        for (int nt = 0; nt < 4; nt++) {
            int row = bm + wm + mt * 16 + lq;
            int col = bn + wn + nt * 8 + lr * 2;
            float b0 = bias[col], b1 = bias[col + 1];
            float v0 = c[mt][nt][0] + b0;
            float v1 = c[mt][nt][1] + b1;
            float v2 = c[mt][nt][2] + b0;
            float v3 = c[mt][nt][3] + b1;
            if (relu) {
                v0 = fmaxf(v0, 0.f); v1 = fmaxf(v1, 0.f);
                v2 = fmaxf(v2, 0.f); v3 = fmaxf(v3, 0.f);
            }
            *(float2*)&C[(size_t)row * N + col]       = make_float2(v0, v1);
            *(float2*)&C[(size_t)(row + 8) * N + col] = make_float2(v2, v3);
        }
    }
}

// ---------------- Q @ K^T scaled ----------------
__global__ void qk_kernel(const float* __restrict__ qkv, float* __restrict__ scores)
{
    int ki = blockIdx.x * 16 + threadIdx.x;
    int qi = blockIdx.y * 16 + threadIdx.y;
    int bh = blockIdx.z;
    if (ki >= Qn || qi >= Qn) return;
    int b = bh >> 3, h = bh & 7;
    const float* qp = qkv + (size_t)(b * Qn + qi) * (3 * Dn) + h * DHn;
    const float* kp = qkv + (size_t)(b * Qn + ki) * (3 * Dn) + Dn + h * DHn;
    float s = 0.f;
#pragma unroll
    for (int d = 0; d < DHn; d++) s += qp[d] * kp[d];
    scores[((size_t)bh * Qn + qi) * Qn + ki] = s * 0.17677669529663689f; // 1/sqrt(32)
}

// ---------------- row softmax over 300, in-place ----------------
__global__ void softmax_kernel(float* __restrict__ sc)
{
    int row = blockIdx.x;
    float* p = sc + (size_t)row * Qn;
    int t = threadIdx.x; // 128
    float v0 = p[t];
    float v1 = p[t + 128];
    float v2 = (t + 256 < Qn) ? p[t + 256] : -1e30f;
    float m = fmaxf(v0, fmaxf(v1, v2));
    __shared__ float red[4];
#pragma unroll
    for (int o = 16; o; o >>= 1) m = fmaxf(m, __shfl_xor_sync(~0u, m, o));
    if ((t & 31) == 0) red[t >> 5] = m;
    __syncthreads();
    m = fmaxf(fmaxf(red[0], red[1]), fmaxf(red[2], red[3]));
    float e0 = expf(v0 - m), e1 = expf(v1 - m);
    float e2 = (t + 256 < Qn) ? expf(v2 - m) : 0.f;
    float su = e0 + e1 + e2;
#pragma unroll
    for (int o = 16; o; o >>= 1) su += __shfl_xor_sync(~0u, su, o);
    __syncthreads();
    if ((t & 31) == 0) red[t >> 5] = su;
    __syncthreads();
    su = red[0] + red[1] + red[2] + red[3];
    float inv = 1.f / su;
    p[t] = e0 * inv;
    p[t + 128] = e1 * inv;
    if (t + 256 < Qn) p[t + 256] = e2 * inv;
}

// ---------------- attn @ V ----------------
__global__ __launch_bounds__(256) void av_kernel(
    const float* __restrict__ qkv, const float* __restrict__ attn, float* __restrict__ sa)
{
    __shared__ float Vs[Qn * DHn];
    int b = blockIdx.x >> 3, h = blockIdx.x & 7;
    int tid = threadIdx.x;
    for (int i = tid; i < Qn * DHn; i += 256) {
        int k = i >> 5, d = i & 31;
        Vs[i] = qkv[(size_t)(b * Qn + k) * (3 * Dn) + 2 * Dn + h * DHn + d];
    }
    __syncthreads();
    int d = tid & 31, qs = tid >> 5;
    for (int q0 = qs; q0 < Qn; q0 += 8) {
        const float* ap = attn + ((size_t)blockIdx.x * Qn + q0) * Qn;
        float acc = 0.f;
        for (int k = 0; k < Qn; k++) acc += ap[k] * Vs[(k << 5) + d];
        sa[(size_t)(b * Qn + q0) * Dn + h * DHn + d] = acc;
    }
}

// ---------------- fused residual-add + LayerNorm ----------------
__global__ void add_ln_kernel(const float* __restrict__ a, const float* __restrict__ r,
                              const float* __restrict__ g, const float* __restrict__ be,
                              float* __restrict__ out)
{
    int row = blockIdx.x, t = threadIdx.x;
    size_t idx = (size_t)row * Dn + t;
    float v = a[idx] + r[idx];
    __shared__ float red[8];
    float s = v;
#pragma unroll
    for (int o = 16; o; o >>= 1) s += __shfl_xor_sync(~0u, s, o);
    if ((t & 31) == 0) red[t >> 5] = s;
    __syncthreads();
    float mean = 0.f;
#pragma unroll
    for (int i = 0; i < 8; i++) mean += red[i];
    mean *= (1.f / Dn);
    float d = v - mean;
    float s2 = d * d;
#pragma unroll
    for (int o = 16; o; o >>= 1) s2 += __shfl_xor_sync(~0u, s2, o);
    __syncthreads();
    if ((t & 31) == 0) red[t >> 5] = s2;
    __syncthreads();
    float var = 0.f;
#pragma unroll
    for (int i = 0; i < 8; i++) var += red[i];
    var *= (1.f / Dn);
    out[idx] = d * rsqrtf(var + LN_EPS) * g[t] + be[t];
}

// ---------------- fused ref/offs/attw matvecs + P-softmax + bilinear sampling ----------------
__global__ __launch_bounds__(256) void refsample_kernel(
    const float* __restrict__ x1,
    const float* __restrict__ ref_w, const float* __restrict__ ref_b,
    const float* __restrict__ off_w, const float* __restrict__ off_b,
    const float* __restrict__ attw_w, const float* __restrict__ attw_b,
    const float* __restrict__ vals, float* __restrict__ ca)
{
    __shared__ float xrow[Dn];
    __shared__ float sref[2];
    __shared__ float soffs[Hn * Pn * 2];
    __shared__ float alog[Hn * Pn];
    __shared__ float swts[Hn * Pn];

    int bq = blockIdx.x;
    int b = bq / Qn;
    int t = threadIdx.x;

    xrow[t] = x1[(size_t)bq * Dn + t];
    __syncthreads();

    if (t < 2) {
        float s = ref_b[t];
        for (int d = 0; d < Dn; d++) s += xrow[d] * ref_w[d * 2 + t];
        sref[t] = 1.f / (1.f + expf(-s));
    } else if (t < 66) {
        int j = t - 2;
        float s = off_b[j];
        for (int d = 0; d < Dn; d++) s += xrow[d] * off_w[d * 64 + j];
        soffs[j] = s;
    } else if (t < 98) {
        int j = t - 66;
        float s = attw_b[j];
        for (int d = 0; d < Dn; d++) s += xrow[d] * attw_w[d * 32 + j];
        alog[j] = s;
    }
    __syncthreads();

    if (t < Hn) {
        float m = alog[t * 4];
#pragma unroll
        for (int p = 1; p < 4; p++) m = fmaxf(m, alog[t * 4 + p]);
        float e[4], su = 0.f;
#pragma unroll
        for (int p = 0; p < 4; p++) { e[p] = expf(alog[t * 4 + p] - m); su += e[p]; }
        float inv = 1.f / su;
#pragma unroll
        for (int p = 0; p < 4; p++) swts[t * 4 + p] = e[p] * inv;
    }
    __syncthreads();

    int h = t >> 5, d = t & 31;
    float rx = sref[0], ry = sref[1];
    const float* vb = vals + (size_t)b * HWn * Dn + h * DHn + d;
    float acc = 0.f;
#pragma unroll
    for (int p = 0; p < Pn; p++) {
        float lx = fminf(fmaxf(rx + soffs[h * 8 + p * 2 + 0], 0.f), 1.f);
        float ly = fminf(fmaxf(ry + soffs[h * 8 + p * 2 + 1], 0.f), 1.f);
        float sx = lx * (float)(WGn - 1);
        float sy = ly * (float)(HGn - 1);
        float x0f = floorf(sx), y0f = floorf(sy);
        int x0 = min(max((int)x0f, 0), WGn - 1);
        int y0 = min(max((int)y0f, 0), HGn - 1);
        int x1i = min(x0 + 1, WGn - 1);
        int y1i = min(y0 + 1, HGn - 1);
        float wx1 = sx - x0f, wx0 = 1.f - wx1;
        float wy1 = sy - y0f, wy0 = 1.f - wy1;
        float v00 = vb[(size_t)(y0 * WGn + x0) * Dn];
        float v01 = vb[(size_t)(y1i * WGn + x0) * Dn];
        float v10 = vb[(size_t)(y0 * WGn + x1i) * Dn];
        float v11 = vb[(size_t)(y1i * WGn + x1i) * Dn];
        float bil = v00 * wx0 * wy0 + v01 * wx0 * wy1 + v10 * wx1 * wy0 + v11 * wx1 * wy1;
        acc += swts[h * 4 + p] * bil;
    }
    ca[(size_t)bq * Dn + t] = acc;
}

// ---------------- launch ----------------
extern "C" void kernel_launch(void* const* d_in, const int* in_sizes, int n_in,
                              void* d_out, int out_size)
{
    const float* tgt        = (const float*)d_in[0];
    const float* memory     = (const float*)d_in[1];
    const float* in_proj_w  = (const float*)d_in[2];
    const float* in_proj_b  = (const float*)d_in[3];
    const float* out_proj_w = (const float*)d_in[4];
    const float* out_proj_b = (const float*)d_in[5];
    const float* norm1_g    = (const float*)d_in[6];
    const float* norm1_b    = (const float*)d_in[7];
    const float* ref_w      = (const float*)d_in[8];
    const float* ref_b      = (const float*)d_in[9];
    const float* off_w      = (const float*)d_in[10];
    const float* off_b      = (const float*)d_in[11];
    const float* attw_w     = (const float*)d_in[12];
    const float* attw_b     = (const float*)d_in[13];
    const float* vproj_w    = (const float*)d_in[14];
    const float* vproj_b    = (const float*)d_in[15];
    const float* oproj_w    = (const float*)d_in[16];
    const float* oproj_b    = (const float*)d_in[17];
    const float* norm2_g    = (const float*)d_in[18];
    const float* norm2_b    = (const float*)d_in[19];
    const float* lin1_w     = (const float*)d_in[20];
    const float* lin1_b     = (const float*)d_in[21];
    const float* lin2_w     = (const float*)d_in[22];
    const float* lin2_b     = (const float*)d_in[23];
    const float* norm3_g    = (const float*)d_in[24];
    const float* norm3_b    = (const float*)d_in[25];
    float* out = (float*)d_out;

    float *qkv, *scores, *sa, *x1, *x2, *tmp, *ca, *vals, *ff;
    cudaGetSymbolAddress((void**)&qkv,    g_qkv);
    cudaGetSymbolAddress((void**)&scores, g_scores);
    cudaGetSymbolAddress((void**)&sa,     g_sa);
    cudaGetSymbolAddress((void**)&x1,     g_x1);
    cudaGetSymbolAddress((void**)&x2,     g_x2);
    cudaGetSymbolAddress((void**)&tmp,    g_tmp);
    cudaGetSymbolAddress((void**)&ca,     g_ca);
    cudaGetSymbolAddress((void**)&vals,   g_vals);
    cudaGetSymbolAddress((void**)&ff,     g_ff);

    // 1. qkv projection [4800,256]@[256,768]
    gemm_tf32_kernel<<<dim3(768 / TBN, BQ / TBM), 256>>>(tgt, in_proj_w, in_proj_b, qkv, BQ, 768, Dn, 0);
    // 2. value projection of memory [160000,256]@[256,256]
    gemm_tf32_kernel<<<dim3(Dn / TBN, MEMROWS / TBM), 256>>>(memory, vproj_w, vproj_b, vals, MEMROWS, Dn, Dn, 0);
    // 3. scores
    qk_kernel<<<dim3((Qn + 15) / 16, (Qn + 15) / 16, Bn * Hn), dim3(16, 16)>>>(qkv, scores);
    // 4. softmax
    softmax_kernel<<<Bn * Hn * Qn, 128>>>(scores);
    // 5. attn @ V
    av_kernel<<<Bn * Hn, 256>>>(qkv, scores, sa);
    // 6. out_proj
    gemm_tf32_kernel<<<dim3(Dn / TBN, BQ / TBM), 256>>>(sa, out_proj_w, out_proj_b, tmp, BQ, Dn, Dn, 0);
    // 7. x1 = LN(tgt + sa_out)
    add_ln_kernel<<<BQ, Dn>>>(tgt, tmp, norm1_g, norm1_b, x1);
    // 8. ref/offsets/weights + sampling -> ca (pre oproj)
    refsample_kernel<<<BQ, Dn>>>(x1, ref_w, ref_b, off_w, off_b, attw_w, attw_b, vals, ca);
    // 9. oproj
    gemm_tf32_kernel<<<dim3(Dn / TBN, BQ / TBM), 256>>>(ca, oproj_w, oproj_b, tmp, BQ, Dn, Dn, 0);
    // 10. x2 = LN(x1 + ca_out)
    add_ln_kernel<<<BQ, Dn>>>(x1, tmp, norm2_g, norm2_b, x2);
    // 11. FFN lin1 + ReLU
    gemm_tf32_kernel<<<dim3(Fn / TBN, BQ / TBM), 256>>>(x2, lin1_w, lin1_b, ff, BQ, Fn, Dn, 1);
    // 12. FFN lin2
    gemm_tf32_kernel<<<dim3(Dn / TBN, BQ / TBM), 256>>>(ff, lin2_w, lin2_b, tmp, BQ, Dn, Fn, 0);
    // 13. out = LN(x2 + ffn)
    add_ln_kernel<<<BQ, Dn>>>(x2, tmp, norm3_g, norm3_b, out);
}

// round 3
// speedup vs baseline: 3.4653x; 2.3470x over previous
#include <cuda_runtime.h>
#include <math.h>
#include <stdint.h>

#define Bn 16
#define Qn 300
#define Dn 256
#define Hn 8
#define Pn 4
#define Fn 2048
#define HGn 100
#define WGn 100
#define HWn 10000
#define DHn 32
#define LN_EPS 1e-5f

#define BQ (Bn*Qn)            // 4800
#define MEMROWS (Bn*HWn)      // 160000

// ---------------- scratch (allocation-free: __device__ globals) ----------------
__device__ float g_qkv[BQ*3*Dn];
__device__ float g_sa[BQ*Dn];
__device__ float g_x1[BQ*Dn];
__device__ float g_x2[BQ*Dn];
__device__ float g_tmp[BQ*Dn];
__device__ float g_ca[BQ*Dn];
__device__ float g_vals[MEMROWS*Dn];
__device__ float g_ff[BQ*Fn];

// ---------------- tf32 tensor-core GEMM (templated tile height) ----------------
// C[M,N] = A[M,K] @ W[K,N] + bias, optional ReLU.
// Block tile (MT*64) x 128, BK=16, 8 warps (2x4), warp tile (MT*32) x 32.
#define TBN 128
#define TBK 16

__device__ __forceinline__ float ftf32(float x) {
    float y;
    asm("cvt.rna.tf32.f32 %0, %1;" : "=f"(y) : "f"(x));
    return y;
}

template<int MT>
__global__ __launch_bounds__(256) void gemm_tf32_kernel(
    const float* __restrict__ A, const float* __restrict__ W,
    const float* __restrict__ bias, float* __restrict__ C,
    int M, int N, int K, int relu)
{
    constexpr int TM = MT * 64;
    __shared__ float As[2][TBK][TM + 4];
    __shared__ float Bs[2][TBK][TBN + 4];

    const int tid  = threadIdx.x;
    const int lane = tid & 31;
    const int warp = tid >> 5;
    const int wm = (warp >> 2) * (MT * 32);
    const int wn = (warp & 3) * 32;
    const int bm = blockIdx.y * TM;
    const int bn = blockIdx.x * TBN;

    const int lq = lane >> 2;   // 0..7
    const int lr = lane & 3;    // 0..3

    const int a_row = tid >> 2;          // 0..63
    const int a_col = (tid & 3) * 4;     // 0,4,8,12
    const int b_row = tid >> 4;          // 0..15
    const int b_col = (tid & 15) * 8;    // 0..120

    const float* Aptr = A + (size_t)(bm + a_row) * K + a_col;
    const float* Wptr = W + (size_t)b_row * N + bn + b_col;

    float c[2 * MT][4][4];
#pragma unroll
    for (int i = 0; i < 2 * MT; i++)
#pragma unroll
        for (int j = 0; j < 4; j++)
#pragma unroll
            for (int l = 0; l < 4; l++) c[i][j][l] = 0.f;

    float4 av[MT], bv0, bv1;
#pragma unroll
    for (int i = 0; i < MT; i++)
        av[i] = *(const float4*)(Aptr + (size_t)i * 64 * K);
    bv0 = *(const float4*)(Wptr);
    bv1 = *(const float4*)(Wptr + 4);
    {
#pragma unroll
        for (int i = 0; i < MT; i++) {
            As[0][a_col + 0][a_row + i * 64] = ftf32(av[i].x);
            As[0][a_col + 1][a_row + i * 64] = ftf32(av[i].y);
            As[0][a_col + 2][a_row + i * 64] = ftf32(av[i].z);
            As[0][a_col + 3][a_row + i * 64] = ftf32(av[i].w);
        }
        float4 t0 = make_float4(ftf32(bv0.x), ftf32(bv0.y), ftf32(bv0.z), ftf32(bv0.w));
        float4 t1 = make_float4(ftf32(bv1.x), ftf32(bv1.y), ftf32(bv1.z), ftf32(bv1.w));
        *(float4*)&Bs[0][b_row][b_col]     = t0;
        *(float4*)&Bs[0][b_row][b_col + 4] = t1;
    }
    __syncthreads();

    int buf = 0;
    for (int kt = 0; kt < K; kt += TBK) {
        const bool has_next = (kt + TBK) < K;
        if (has_next) {
#pragma unroll
            for (int i = 0; i < MT; i++)
                av[i] = *(const float4*)(Aptr + (size_t)i * 64 * K + kt + TBK);
            bv0 = *(const float4*)(Wptr + (size_t)(kt + TBK) * N);
            bv1 = *(const float4*)(Wptr + (size_t)(kt + TBK) * N + 4);
        }

#pragma unroll
        for (int ks = 0; ks < TBK; ks += 8) {
            uint32_t a[2 * MT][4], b[4][2];
#pragma unroll
            for (int mt = 0; mt < 2 * MT; mt++) {
                int mr = wm + mt * 16 + lq;
                a[mt][0] = __float_as_uint(As[buf][ks + lr    ][mr]);
                a[mt][1] = __float_as_uint(As[buf][ks + lr    ][mr + 8]);
                a[mt][2] = __float_as_uint(As[buf][ks + lr + 4][mr]);
                a[mt][3] = __float_as_uint(As[buf][ks + lr + 4][mr + 8]);
            }
#pragma unroll
            for (int nt = 0; nt < 4; nt++) {
                int nc = wn + nt * 8 + lq;
                b[nt][0] = __float_as_uint(Bs[buf][ks + lr    ][nc]);
                b[nt][1] = __float_as_uint(Bs[buf][ks + lr + 4][nc]);
            }
#pragma unroll
            for (int mt = 0; mt < 2 * MT; mt++)
#pragma unroll
                for (int nt = 0; nt < 4; nt++) {
                    asm volatile(
                        "mma.sync.aligned.m16n8k8.row.col.f32.tf32.tf32.f32 "
                        "{%0,%1,%2,%3}, {%4,%5,%6,%7}, {%8,%9}, {%0,%1,%2,%3};"
                        : "+f"(c[mt][nt][0]), "+f"(c[mt][nt][1]),
                          "+f"(c[mt][nt][2]), "+f"(c[mt][nt][3])
                        : "r"(a[mt][0]), "r"(a[mt][1]), "r"(a[mt][2]), "r"(a[mt][3]),
                          "r"(b[nt][0]), "r"(b[nt][1]));
                }
        }

        if (has_next) {
            int nb = buf ^ 1;
#pragma unroll
            for (int i = 0; i < MT; i++) {
                As[nb][a_col + 0][a_row + i * 64] = ftf32(av[i].x);
                As[nb][a_col + 1][a_row + i * 64] = ftf32(av[i].y);
                As[nb][a_col + 2][a_row + i * 64] = ftf32(av[i].z);
                As[nb][a_col + 3][a_row + i * 64] = ftf32(av[i].w);
            }
            float4 t0 = make_float4(ftf32(bv0.x), ftf32(bv0.y), ftf32(bv0.z), ftf32(bv0.w));
            float4 t1 = make_float4(ftf32(bv1.x), ftf32(bv1.y), ftf32(bv1.z), ftf32(bv1.w));
            *(float4*)&Bs[nb][b_row][b_col]     = t0;
            *(float4*)&Bs[nb][b_row][b_col + 4] = t1;
        }
        __syncthreads();
        buf ^= 1;
    }

#pragma unroll
    for (int mt = 0; mt < 2 * MT; mt++) {
#pragma unroll
        for (int nt = 0; nt < 4; nt++) {
            int row = bm + wm + mt * 16 + lq;
            int col = bn + wn + nt * 8 + lr * 2;
            float b0 = bias[col], b1 = bias[col + 1];
            float v0 = c[mt][nt][0] + b0;
            float v1 = c[mt][nt][1] + b1;
            float v2 = c[mt][nt][2] + b0;
            float v3 = c[mt][nt][3] + b1;
            if (relu) {
                v0 = fmaxf(v0, 0.f); v1 = fmaxf(v1, 0.f);
                v2 = fmaxf(v2, 0.f); v3 = fmaxf(v3, 0.f);
            }
            *(float2*)&C[(size_t)row * N + col]       = make_float2(v0, v1);
            *(float2*)&C[(size_t)(row + 8) * N + col] = make_float2(v2, v3);
        }
    }
}

// ---------------- fused flash self-attention ----------------
// One thread = one query row (DH=32 in registers). grid = (ceil(Q/128), B*H).
#define KT 60   // key tile (300 = 5*60)

__global__ __launch_bounds__(128) void flash_kernel(
    const float* __restrict__ qkv, float* __restrict__ sa)
{
    __shared__ float Ks[KT][DHn];
    __shared__ float Vs[KT][DHn];

    const int bh = blockIdx.y;
    const int b = bh >> 3, h = bh & 7;
    const int qi = blockIdx.x * 128 + threadIdx.x;
    const bool act = qi < Qn;
    const int tid = threadIdx.x;

    float q[DHn], acc[DHn];
    const float* qp = qkv + (size_t)(b * Qn + (act ? qi : 0)) * (3 * Dn) + h * DHn;
#pragma unroll
    for (int d = 0; d < DHn; d += 4) {
        float4 v = *(const float4*)(qp + d);
        q[d] = v.x; q[d+1] = v.y; q[d+2] = v.z; q[d+3] = v.w;
    }
#pragma unroll
    for (int d = 0; d < DHn; d++) acc[d] = 0.f;

    float m = -1e30f, su = 0.f;
    const float scale = 0.17677669529663689f; // 1/sqrt(32)

    const float* kbase = qkv + (size_t)(b * Qn) * (3 * Dn) + Dn + h * DHn;
    const float* vbase = kbase + Dn;

    for (int t0 = 0; t0 < Qn; t0 += KT) {
        // cooperative tile load: KT rows x 8 float4 each
        for (int i = tid; i < KT * 8; i += 128) {
            int j = i >> 3, dc = (i & 7) * 4;
            size_t off = (size_t)(t0 + j) * (3 * Dn) + dc;
            *(float4*)&Ks[j][dc] = *(const float4*)(kbase + off);
            *(float4*)&Vs[j][dc] = *(const float4*)(vbase + off);
        }
        __syncthreads();

#pragma unroll 4
        for (int j = 0; j < KT; j++) {
            float s = 0.f;
#pragma unroll
            for (int d = 0; d < DHn; d++) s += q[d] * Ks[j][d];
            s *= scale;
            float mn = fmaxf(m, s);
            float corr = __expf(m - mn);
            float p = __expf(s - mn);
            su = su * corr + p;
#pragma unroll
            for (int d = 0; d < DHn; d++) acc[d] = acc[d] * corr + p * Vs[j][d];
            m = mn;
        }
        __syncthreads();
    }

    if (act) {
        float inv = 1.f / su;
        float* op = sa + (size_t)(b * Qn + qi) * Dn + h * DHn;
#pragma unroll
        for (int d = 0; d < DHn; d += 4) {
            float4 v = make_float4(acc[d]*inv, acc[d+1]*inv, acc[d+2]*inv, acc[d+3]*inv);
            *(float4*)(op + d) = v;
        }
    }
}

// ---------------- fused residual-add + LayerNorm ----------------
__global__ void add_ln_kernel(const float* __restrict__ a, const float* __restrict__ r,
                              const float* __restrict__ g, const float* __restrict__ be,
                              float* __restrict__ out)
{
    int row = blockIdx.x, t = threadIdx.x;
    size_t idx = (size_t)row * Dn + t;
    float v = a[idx] + r[idx];
    __shared__ float red[8];
    float s = v;
#pragma unroll
    for (int o = 16; o; o >>= 1) s += __shfl_xor_sync(~0u, s, o);
    if ((t & 31) == 0) red[t >> 5] = s;
    __syncthreads();
    float mean = 0.f;
#pragma unroll
    for (int i = 0; i < 8; i++) mean += red[i];
    mean *= (1.f / Dn);
    float d = v - mean;
    float s2 = d * d;
#pragma unroll
    for (int o = 16; o; o >>= 1) s2 += __shfl_xor_sync(~0u, s2, o);
    __syncthreads();
    if ((t & 31) == 0) red[t >> 5] = s2;
    __syncthreads();
    float var = 0.f;
#pragma unroll
    for (int i = 0; i < 8; i++) var += red[i];
    var *= (1.f / Dn);
    out[idx] = d * rsqrtf(var + LN_EPS) * g[t] + be[t];
}

// ---------------- fused ref/offs/attw matvecs + P-softmax + bilinear sampling ----------------
__global__ __launch_bounds__(256) void refsample_kernel(
    const float* __restrict__ x1,
    const float* __restrict__ ref_w, const float* __restrict__ ref_b,
    const float* __restrict__ off_w, const float* __restrict__ off_b,
    const float* __restrict__ attw_w, const float* __restrict__ attw_b,
    const float* __restrict__ vals, float* __restrict__ ca)
{
    __shared__ float xrow[Dn];
    __shared__ float sref[2];
    __shared__ float soffs[Hn * Pn * 2];
    __shared__ float alog[Hn * Pn];
    __shared__ float swts[Hn * Pn];

    int bq = blockIdx.x;
    int b = bq / Qn;
    int t = threadIdx.x;

    xrow[t] = x1[(size_t)bq * Dn + t];
    __syncthreads();

    if (t < 2) {
        float s = ref_b[t];
        for (int d = 0; d < Dn; d++) s += xrow[d] * ref_w[d * 2 + t];
        sref[t] = 1.f / (1.f + expf(-s));
    } else if (t < 66) {
        int j = t - 2;
        float s = off_b[j];
        for (int d = 0; d < Dn; d++) s += xrow[d] * off_w[d * 64 + j];
        soffs[j] = s;
    } else if (t < 98) {
        int j = t - 66;
        float s = attw_b[j];
        for (int d = 0; d < Dn; d++) s += xrow[d] * attw_w[d * 32 + j];
        alog[j] = s;
    }
    __syncthreads();

    if (t < Hn) {
        float m = alog[t * 4];
#pragma unroll
        for (int p = 1; p < 4; p++) m = fmaxf(m, alog[t * 4 + p]);
        float e[4], su = 0.f;
#pragma unroll
        for (int p = 0; p < 4; p++) { e[p] = expf(alog[t * 4 + p] - m); su += e[p]; }
        float inv = 1.f / su;
#pragma unroll
        for (int p = 0; p < 4; p++) swts[t * 4 + p] = e[p] * inv;
    }
    __syncthreads();

    int h = t >> 5, d = t & 31;
    float rx = sref[0], ry = sref[1];
    const float* vb = vals + (size_t)b * HWn * Dn + h * DHn + d;
    float acc = 0.f;
#pragma unroll
    for (int p = 0; p < Pn; p++) {
        float lx = fminf(fmaxf(rx + soffs[h * 8 + p * 2 + 0], 0.f), 1.f);
        float ly = fminf(fmaxf(ry + soffs[h * 8 + p * 2 + 1], 0.f), 1.f);
        float sx = lx * (float)(WGn - 1);
        float sy = ly * (float)(HGn - 1);
        float x0f = floorf(sx), y0f = floorf(sy);
        int x0 = min(max((int)x0f, 0), WGn - 1);
        int y0 = min(max((int)y0f, 0), HGn - 1);
        int x1i = min(x0 + 1, WGn - 1);
        int y1i = min(y0 + 1, HGn - 1);
        float wx1 = sx - x0f, wx0 = 1.f - wx1;
        float wy1 = sy - y0f, wy0 = 1.f - wy1;
        float v00 = vb[(size_t)(y0 * WGn + x0) * Dn];
        float v01 = vb[(size_t)(y1i * WGn + x0) * Dn];
        float v10 = vb[(size_t)(y0 * WGn + x1i) * Dn];
        float v11 = vb[(size_t)(y1i * WGn + x1i) * Dn];
        float bil = v00 * wx0 * wy0 + v01 * wx0 * wy1 + v10 * wx1 * wy0 + v11 * wx1 * wy1;
        acc += swts[h * 4 + p] * bil;
    }
    ca[(size_t)bq * Dn + t] = acc;
}

// ---------------- launch ----------------
extern "C" void kernel_launch(void* const* d_in, const int* in_sizes, int n_in,
                              void* d_out, int out_size)
{
    const float* tgt        = (const float*)d_in[0];
    const float* memory     = (const float*)d_in[1];
    const float* in_proj_w  = (const float*)d_in[2];
    const float* in_proj_b  = (const float*)d_in[3];
    const float* out_proj_w = (const float*)d_in[4];
    const float* out_proj_b = (const float*)d_in[5];
    const float* norm1_g    = (const float*)d_in[6];
    const float* norm1_b    = (const float*)d_in[7];
    const float* ref_w      = (const float*)d_in[8];
    const float* ref_b      = (const float*)d_in[9];
    const float* off_w      = (const float*)d_in[10];
    const float* off_b      = (const float*)d_in[11];
    const float* attw_w     = (const float*)d_in[12];
    const float* attw_b     = (const float*)d_in[13];
    const float* vproj_w    = (const float*)d_in[14];
    const float* vproj_b    = (const float*)d_in[15];
    const float* oproj_w    = (const float*)d_in[16];
    const float* oproj_b    = (const float*)d_in[17];
    const float* norm2_g    = (const float*)d_in[18];
    const float* norm2_b    = (const float*)d_in[19];
    const float* lin1_w     = (const float*)d_in[20];
    const float* lin1_b     = (const float*)d_in[21];
    const float* lin2_w     = (const float*)d_in[22];
    const float* lin2_b     = (const float*)d_in[23];
    const float* norm3_g    = (const float*)d_in[24];
    const float* norm3_b    = (const float*)d_in[25];
    float* out = (float*)d_out;

    float *qkv, *sa, *x1, *x2, *tmp, *ca, *vals, *ff;
    cudaGetSymbolAddress((void**)&qkv,    g_qkv);
    cudaGetSymbolAddress((void**)&sa,     g_sa);
    cudaGetSymbolAddress((void**)&x1,     g_x1);
    cudaGetSymbolAddress((void**)&x2,     g_x2);
    cudaGetSymbolAddress((void**)&tmp,    g_tmp);
    cudaGetSymbolAddress((void**)&ca,     g_ca);
    cudaGetSymbolAddress((void**)&vals,   g_vals);
    cudaGetSymbolAddress((void**)&ff,     g_ff);

    // 1. qkv projection [4800,256]@[256,768]
    gemm_tf32_kernel<1><<<dim3(768 / TBN, BQ / 64), 256>>>(tgt, in_proj_w, in_proj_b, qkv, BQ, 768, Dn, 0);
    // 2. value projection of memory [160000,256]@[256,256] (128-row tiles)
    gemm_tf32_kernel<2><<<dim3(Dn / TBN, MEMROWS / 128), 256>>>(memory, vproj_w, vproj_b, vals, MEMROWS, Dn, Dn, 0);
    // 3. fused self-attention (qk + softmax + av)
    flash_kernel<<<dim3((Qn + 127) / 128, Bn * Hn), 128>>>(qkv, sa);
    // 4. out_proj
    gemm_tf32_kernel<1><<<dim3(Dn / TBN, BQ / 64), 256>>>(sa, out_proj_w, out_proj_b, tmp, BQ, Dn, Dn, 0);
    // 5. x1 = LN(tgt + sa_out)
    add_ln_kernel<<<BQ, Dn>>>(tgt, tmp, norm1_g, norm1_b, x1);
    // 6. ref/offsets/weights + sampling -> ca
    refsample_kernel<<<BQ, Dn>>>(x1, ref_w, ref_b, off_w, off_b, attw_w, attw_b, vals, ca);
    // 7. oproj
    gemm_tf32_kernel<1><<<dim3(Dn / TBN, BQ / 64), 256>>>(ca, oproj_w, oproj_b, tmp, BQ, Dn, Dn, 0);
    // 8. x2 = LN(x1 + ca_out)
    add_ln_kernel<<<BQ, Dn>>>(x1, tmp, norm2_g, norm2_b, x2);
    // 9. FFN lin1 + ReLU
    gemm_tf32_kernel<1><<<dim3(Fn / TBN, BQ / 64), 256>>>(x2, lin1_w, lin1_b, ff, BQ, Fn, Dn, 1);
    // 10. FFN lin2
    gemm_tf32_kernel<1><<<dim3(Dn / TBN, BQ / 64), 256>>>(ff, lin2_w, lin2_b, tmp, BQ, Dn, Fn, 0);
    // 11. out = LN(x2 + ffn)
    add_ln_kernel<<<BQ, Dn>>>(x2, tmp, norm3_g, norm3_b, out);
}

// round 5
// speedup vs baseline: 4.5138x; 1.3026x over previous
#include <cuda_runtime.h>
#include <math.h>
#include <stdint.h>

#define Bn 16
#define Qn 300
#define Dn 256
#define Hn 8
#define Pn 4
#define Fn 2048
#define HGn 100
#define WGn 100
#define HWn 10000
#define DHn 32
#define LN_EPS 1e-5f

#define BQ (Bn*Qn)            // 4800
#define MEMROWS (Bn*HWn)      // 160000

// ---------------- scratch (allocation-free: __device__ globals) ----------------
__device__ float g_qkv[BQ*3*Dn];
__device__ float g_sa[BQ*Dn];
__device__ float g_x1[BQ*Dn];
__device__ float g_x2[BQ*Dn];
__device__ float g_tmp[BQ*Dn];
__device__ float g_ca[BQ*Dn];
__device__ float g_vals[MEMROWS*Dn];
__device__ float g_ff[BQ*Fn];
__device__ float g_wcat[Dn*128];
__device__ float g_bcat[128];
__device__ float g_lg[BQ*128];

// ---------------- tf32 tensor-core GEMM, cp.async 3-stage pipeline ----------------
// C[M,N] = A[M,K] @ W[K,N] + bias, optional ReLU.
// Block tile (MT*64) x 128, BK=16, 8 warps (2x4), warp tile (MT*32) x 32.
// A staged [m][k] (pitch 20), B staged [k][n] (pitch 136); raw f32 in smem,
// cvt.rna.tf32 applied at fragment load (round-to-nearest numerics).
#define TBN 128
#define TBK 16
#define APITCH (TBK + 4)    // 20
#define BPITCH (TBN + 8)    // 136

__device__ __forceinline__ void cp16(void* dst, const void* src) {
    uint32_t d = (uint32_t)__cvta_generic_to_shared(dst);
    asm volatile("cp.async.ca.shared.global [%0], [%1], 16;" :: "r"(d), "l"(src));
}

__device__ __forceinline__ uint32_t tf32r(float x) {
    float y;
    asm("cvt.rna.tf32.f32 %0, %1;" : "=f"(y) : "f"(x));
    return __float_as_uint(y);
}

template<int MT>
__global__ __launch_bounds__(256) void gemm_tf32_async(
    const float* __restrict__ A, const float* __restrict__ W,
    const float* __restrict__ bias, float* __restrict__ C,
    int M, int N, int K, int relu)
{
    constexpr int TM = MT * 64;
    extern __shared__ float smem[];
    float (*As)[TM][APITCH] = (float(*)[TM][APITCH])smem;
    float (*Bs)[TBK][BPITCH] = (float(*)[TBK][BPITCH])(smem + 3 * TM * APITCH);

    const int tid  = threadIdx.x;
    const int lane = tid & 31;
    const int warp = tid >> 5;
    const int wm = (warp >> 2) * (MT * 32);
    const int wn = (warp & 3) * 32;
    const int bm = blockIdx.y * TM;
    const int bn = blockIdx.x * TBN;

    const int lq = lane >> 2;   // 0..7
    const int lr = lane & 3;    // 0..3

    const int a_row = tid >> 2;          // 0..63
    const int a_col = (tid & 3) * 4;     // 0,4,8,12
    const int b_row = tid >> 4;          // 0..15
    const int b_col = (tid & 15) * 8;    // 0..120

    const float* Aptr = A + (size_t)(bm + a_row) * K + a_col;
    const float* Wptr = W + (size_t)b_row * N + bn + b_col;

    float c[2 * MT][4][4];
#pragma unroll
    for (int i = 0; i < 2 * MT; i++)
#pragma unroll
        for (int j = 0; j < 4; j++)
#pragma unroll
            for (int l = 0; l < 4; l++) c[i][j][l] = 0.f;

    const int nk = K / TBK;

    // prologue: stages 0,1
#pragma unroll
    for (int s = 0; s < 2; s++) {
        int kt = s * TBK;
#pragma unroll
        for (int i = 0; i < MT; i++)
            cp16(&As[s][a_row + i * 64][a_col], Aptr + (size_t)i * 64 * K + kt);
        cp16(&Bs[s][b_row][b_col],     Wptr + (size_t)kt * N);
        cp16(&Bs[s][b_row][b_col + 4], Wptr + (size_t)kt * N + 4);
        asm volatile("cp.async.commit_group;" ::: "memory");
    }

    for (int it = 0; it < nk; it++) {
        asm volatile("cp.async.wait_group 1;" ::: "memory");
        __syncthreads();

        int nxt = it + 2;
        if (nxt < nk) {
            int s = nxt % 3;
            int kt = nxt * TBK;
#pragma unroll
            for (int i = 0; i < MT; i++)
                cp16(&As[s][a_row + i * 64][a_col], Aptr + (size_t)i * 64 * K + kt);
            cp16(&Bs[s][b_row][b_col],     Wptr + (size_t)kt * N);
            cp16(&Bs[s][b_row][b_col + 4], Wptr + (size_t)kt * N + 4);
        }
        asm volatile("cp.async.commit_group;" ::: "memory");

        const int buf = it % 3;
#pragma unroll
        for (int ks = 0; ks < TBK; ks += 8) {
            uint32_t a[2 * MT][4], b[4][2];
#pragma unroll
            for (int mt = 0; mt < 2 * MT; mt++) {
                int mr = wm + mt * 16 + lq;
                a[mt][0] = tf32r(As[buf][mr    ][ks + lr]);
                a[mt][1] = tf32r(As[buf][mr + 8][ks + lr]);
                a[mt][2] = tf32r(As[buf][mr    ][ks + lr + 4]);
                a[mt][3] = tf32r(As[buf][mr + 8][ks + lr + 4]);
            }
#pragma unroll
            for (int nt = 0; nt < 4; nt++) {
                int nc = wn + nt * 8 + lq;
                b[nt][0] = tf32r(Bs[buf][ks + lr    ][nc]);
                b[nt][1] = tf32r(Bs[buf][ks + lr + 4][nc]);
            }
#pragma unroll
            for (int mt = 0; mt < 2 * MT; mt++)
#pragma unroll
                for (int nt = 0; nt < 4; nt++) {
                    asm volatile(
                        "mma.sync.aligned.m16n8k8.row.col.f32.tf32.tf32.f32 "
                        "{%0,%1,%2,%3}, {%4,%5,%6,%7}, {%8,%9}, {%0,%1,%2,%3};"
                        : "+f"(c[mt][nt][0]), "+f"(c[mt][nt][1]),
                          "+f"(c[mt][nt][2]), "+f"(c[mt][nt][3])
                        : "r"(a[mt][0]), "r"(a[mt][1]), "r"(a[mt][2]), "r"(a[mt][3]),
                          "r"(b[nt][0]), "r"(b[nt][1]));
                }
        }
    }

#pragma unroll
    for (int mt = 0; mt < 2 * MT; mt++) {
#pragma unroll
        for (int nt = 0; nt < 4; nt++) {
            int row = bm + wm + mt * 16 + lq;
            int col = bn + wn + nt * 8 + lr * 2;
            float b0 = bias[col], b1 = bias[col + 1];
            float v0 = c[mt][nt][0] + b0;
            float v1 = c[mt][nt][1] + b1;
            float v2 = c[mt][nt][2] + b0;
            float v3 = c[mt][nt][3] + b1;
            if (relu) {
                v0 = fmaxf(v0, 0.f); v1 = fmaxf(v1, 0.f);
                v2 = fmaxf(v2, 0.f); v3 = fmaxf(v3, 0.f);
            }
            *(float2*)&C[(size_t)row * N + col]       = make_float2(v0, v1);
            *(float2*)&C[(size_t)(row + 8) * N + col] = make_float2(v2, v3);
        }
    }
}

// ---------------- concat ref/off/attw weights into padded [256,128] ----------------
__global__ void concat_w_kernel(
    const float* __restrict__ ref_w, const float* __restrict__ ref_b,
    const float* __restrict__ off_w, const float* __restrict__ off_b,
    const float* __restrict__ attw_w, const float* __restrict__ attw_b,
    float* __restrict__ Wc, float* __restrict__ bc)
{
    int i = blockIdx.x * 256 + threadIdx.x;
    if (i < Dn * 128) {
        int d = i >> 7, j = i & 127;
        float v = 0.f;
        if (j < 2) v = ref_w[d * 2 + j];
        else if (j < 66) v = off_w[d * 64 + (j - 2)];
        else if (j < 98) v = attw_w[d * 32 + (j - 66)];
        Wc[i] = v;
    }
    if (i < 128) {
        float v = 0.f;
        if (i < 2) v = ref_b[i];
        else if (i < 66) v = off_b[i - 2];
        else if (i < 98) v = attw_b[i - 66];
        bc[i] = v;
    }
}

// ---------------- fused flash self-attention ----------------
#define KT 60   // key tile (300 = 5*60)

__global__ __launch_bounds__(128) void flash_kernel(
    const float* __restrict__ qkv, float* __restrict__ sa)
{
    __shared__ float Ks[KT][DHn];
    __shared__ float Vs[KT][DHn];

    const int bh = blockIdx.y;
    const int b = bh >> 3, h = bh & 7;
    const int qi = blockIdx.x * 128 + threadIdx.x;
    const bool act = qi < Qn;
    const int tid = threadIdx.x;

    float q[DHn], acc[DHn];
    const float* qp = qkv + (size_t)(b * Qn + (act ? qi : 0)) * (3 * Dn) + h * DHn;
#pragma unroll
    for (int d = 0; d < DHn; d += 4) {
        float4 v = *(const float4*)(qp + d);
        q[d] = v.x; q[d+1] = v.y; q[d+2] = v.z; q[d+3] = v.w;
    }
#pragma unroll
    for (int d = 0; d < DHn; d++) acc[d] = 0.f;

    float m = -1e30f, su = 0.f;
    const float scale = 0.17677669529663689f;

    const float* kbase = qkv + (size_t)(b * Qn) * (3 * Dn) + Dn + h * DHn;
    const float* vbase = kbase + Dn;

    for (int t0 = 0; t0 < Qn; t0 += KT) {
        for (int i = tid; i < KT * 8; i += 128) {
            int j = i >> 3, dc = (i & 7) * 4;
            size_t off = (size_t)(t0 + j) * (3 * Dn) + dc;
            *(float4*)&Ks[j][dc] = *(const float4*)(kbase + off);
            *(float4*)&Vs[j][dc] = *(const float4*)(vbase + off);
        }
        __syncthreads();

#pragma unroll 4
        for (int j = 0; j < KT; j++) {
            float s = 0.f;
#pragma unroll
            for (int d = 0; d < DHn; d++) s += q[d] * Ks[j][d];
            s *= scale;
            float mn = fmaxf(m, s);
            float corr = __expf(m - mn);
            float p = __expf(s - mn);
            su = su * corr + p;
#pragma unroll
            for (int d = 0; d < DHn; d++) acc[d] = acc[d] * corr + p * Vs[j][d];
            m = mn;
        }
        __syncthreads();
    }

    if (act) {
        float inv = 1.f / su;
        float* op = sa + (size_t)(b * Qn + qi) * Dn + h * DHn;
#pragma unroll
        for (int d = 0; d < DHn; d += 4) {
            float4 v = make_float4(acc[d]*inv, acc[d+1]*inv, acc[d+2]*inv, acc[d+3]*inv);
            *(float4*)(op + d) = v;
        }
    }
}

// ---------------- fused residual-add + LayerNorm ----------------
__global__ void add_ln_kernel(const float* __restrict__ a, const float* __restrict__ r,
                              const float* __restrict__ g, const float* __restrict__ be,
                              float* __restrict__ out)
{
    int row = blockIdx.x, t = threadIdx.x;
    size_t idx = (size_t)row * Dn + t;
    float v = a[idx] + r[idx];
    __shared__ float red[8];
    float s = v;
#pragma unroll
    for (int o = 16; o; o >>= 1) s += __shfl_xor_sync(~0u, s, o);
    if ((t & 31) == 0) red[t >> 5] = s;
    __syncthreads();
    float mean = 0.f;
#pragma unroll
    for (int i = 0; i < 8; i++) mean += red[i];
    mean *= (1.f / Dn);
    float d = v - mean;
    float s2 = d * d;
#pragma unroll
    for (int o = 16; o; o >>= 1) s2 += __shfl_xor_sync(~0u, s2, o);
    __syncthreads();
    if ((t & 31) == 0) red[t >> 5] = s2;
    __syncthreads();
    float var = 0.f;
#pragma unroll
    for (int i = 0; i < 8; i++) var += red[i];
    var *= (1.f / Dn);
    out[idx] = d * rsqrtf(var + LN_EPS) * g[t] + be[t];
}

// ---------------- sampler: sigmoid/softmax + bilinear gather (logits precomputed) ----
__global__ __launch_bounds__(256) void sampler_kernel(
    const float* __restrict__ lgbuf, const float* __restrict__ vals,
    float* __restrict__ ca)
{
    __shared__ float lg[128];
    __shared__ float sref[2];
    __shared__ float swts[Hn * Pn];

    int bq = blockIdx.x;
    int b = bq / Qn;
    int t = threadIdx.x;

    if (t < 128) lg[t] = lgbuf[(size_t)bq * 128 + t];
    __syncthreads();

    if (t < 2) sref[t] = 1.f / (1.f + expf(-lg[t]));
    else if (t >= 32 && t < 40) {
        int h = t - 32;
        const float* al = &lg[66 + h * 4];
        float m = fmaxf(fmaxf(al[0], al[1]), fmaxf(al[2], al[3]));
        float e0 = expf(al[0]-m), e1 = expf(al[1]-m), e2 = expf(al[2]-m), e3 = expf(al[3]-m);
        float inv = 1.f / (e0 + e1 + e2 + e3);
        swts[h*4+0] = e0*inv; swts[h*4+1] = e1*inv; swts[h*4+2] = e2*inv; swts[h*4+3] = e3*inv;
    }
    __syncthreads();

    int h = t >> 5, d = t & 31;
    float rx = sref[0], ry = sref[1];
    const float* vb = vals + (size_t)b * HWn * Dn + h * DHn + d;
    float acc = 0.f;
#pragma unroll
    for (int p = 0; p < Pn; p++) {
        float lx = fminf(fmaxf(rx + lg[2 + h * 8 + p * 2 + 0], 0.f), 1.f);
        float ly = fminf(fmaxf(ry + lg[2 + h * 8 + p * 2 + 1], 0.f), 1.f);
        float sx = lx * (float)(WGn - 1);
        float sy = ly * (float)(HGn - 1);
        float x0f = floorf(sx), y0f = floorf(sy);
        int x0 = min(max((int)x0f, 0), WGn - 1);
        int y0 = min(max((int)y0f, 0), HGn - 1);
        int x1i = min(x0 + 1, WGn - 1);
        int y1i = min(y0 + 1, HGn - 1);
        float wx1 = sx - x0f, wx0 = 1.f - wx1;
        float wy1 = sy - y0f, wy0 = 1.f - wy1;
        float v00 = vb[(size_t)(y0  * WGn + x0 ) * Dn];
        float v01 = vb[(size_t)(y1i * WGn + x0 ) * Dn];
        float v10 = vb[(size_t)(y0  * WGn + x1i) * Dn];
        float v11 = vb[(size_t)(y1i * WGn + x1i) * Dn];
        float bil = v00 * wx0 * wy0 + v01 * wx0 * wy1 + v10 * wx1 * wy0 + v11 * wx1 * wy1;
        acc += swts[h * 4 + p] * bil;
    }
    ca[(size_t)bq * Dn + t] = acc;
}

// ---------------- launch ----------------
extern "C" void kernel_launch(void* const* d_in, const int* in_sizes, int n_in,
                              void* d_out, int out_size)
{
    const float* tgt        = (const float*)d_in[0];
    const float* memory     = (const float*)d_in[1];
    const float* in_proj_w  = (const float*)d_in[2];
    const float* in_proj_b  = (const float*)d_in[3];
    const float* out_proj_w = (const float*)d_in[4];
    const float* out_proj_b = (const float*)d_in[5];
    const float* norm1_g    = (const float*)d_in[6];
    const float* norm1_b    = (const float*)d_in[7];
    const float* ref_w      = (const float*)d_in[8];
    const float* ref_b      = (const float*)d_in[9];
    const float* off_w      = (const float*)d_in[10];
    const float* off_b      = (const float*)d_in[11];
    const float* attw_w     = (const float*)d_in[12];
    const float* attw_b     = (const float*)d_in[13];
    const float* vproj_w    = (const float*)d_in[14];
    const float* vproj_b    = (const float*)d_in[15];
    const float* oproj_w    = (const float*)d_in[16];
    const float* oproj_b    = (const float*)d_in[17];
    const float* norm2_g    = (const float*)d_in[18];
    const float* norm2_b    = (const float*)d_in[19];
    const float* lin1_w     = (const float*)d_in[20];
    const float* lin1_b     = (const float*)d_in[21];
    const float* lin2_w     = (const float*)d_in[22];
    const float* lin2_b     = (const float*)d_in[23];
    const float* norm3_g    = (const float*)d_in[24];
    const float* norm3_b    = (const float*)d_in[25];
    float* out = (float*)d_out;

    float *qkv, *sa, *x1, *x2, *tmp, *ca, *vals, *ff, *wcat, *bcat, *lgb;
    cudaGetSymbolAddress((void**)&qkv,  g_qkv);
    cudaGetSymbolAddress((void**)&sa,   g_sa);
    cudaGetSymbolAddress((void**)&x1,   g_x1);
    cudaGetSymbolAddress((void**)&x2,   g_x2);
    cudaGetSymbolAddress((void**)&tmp,  g_tmp);
    cudaGetSymbolAddress((void**)&ca,   g_ca);
    cudaGetSymbolAddress((void**)&vals, g_vals);
    cudaGetSymbolAddress((void**)&ff,   g_ff);
    cudaGetSymbolAddress((void**)&wcat, g_wcat);
    cudaGetSymbolAddress((void**)&bcat, g_bcat);
    cudaGetSymbolAddress((void**)&lgb,  g_lg);

    const int smem1 = (3 * 64  * APITCH + 3 * TBK * BPITCH) * 4;  // 41472
    const int smem2 = (3 * 128 * APITCH + 3 * TBK * BPITCH) * 4;  // 56832
    cudaFuncSetAttribute(gemm_tf32_async<1>, cudaFuncAttributeMaxDynamicSharedMemorySize, smem1);
    cudaFuncSetAttribute(gemm_tf32_async<2>, cudaFuncAttributeMaxDynamicSharedMemorySize, smem2);

    // 0. concat ref/off/attw weights (needed before logits GEMM)
    concat_w_kernel<<<128, 256>>>(ref_w, ref_b, off_w, off_b, attw_w, attw_b, wcat, bcat);
    // 1. qkv projection [4800,256]@[256,768]
    gemm_tf32_async<1><<<dim3(768 / TBN, BQ / 64), 256, smem1>>>(tgt, in_proj_w, in_proj_b, qkv, BQ, 768, Dn, 0);
    // 2. value projection of memory [160000,256]@[256,256]
    gemm_tf32_async<2><<<dim3(Dn / TBN, MEMROWS / 128), 256, smem2>>>(memory, vproj_w, vproj_b, vals, MEMROWS, Dn, Dn, 0);
    // 3. fused self-attention
    flash_kernel<<<dim3((Qn + 127) / 128, Bn * Hn), 128>>>(qkv, sa);
    // 4. out_proj
    gemm_tf32_async<1><<<dim3(Dn / TBN, BQ / 64), 256, smem1>>>(sa, out_proj_w, out_proj_b, tmp, BQ, Dn, Dn, 0);
    // 5. x1 = LN(tgt + sa_out)
    add_ln_kernel<<<BQ, Dn>>>(tgt, tmp, norm1_g, norm1_b, x1);
    // 6. logits = x1 @ Wcat + bcat  [4800,256]@[256,128]
    gemm_tf32_async<1><<<dim3(1, BQ / 64), 256, smem1>>>(x1, wcat, bcat, lgb, BQ, 128, Dn, 0);
    // 7. sampler -> ca
    sampler_kernel<<<BQ, 256>>>(lgb, vals, ca);
    // 8. oproj
    gemm_tf32_async<1><<<dim3(Dn / TBN, BQ / 64), 256, smem1>>>(ca, oproj_w, oproj_b, tmp, BQ, Dn, Dn, 0);
    // 9. x2 = LN(x1 + ca_out)
    add_ln_kernel<<<BQ, Dn>>>(x1, tmp, norm2_g, norm2_b, x2);
    // 10. FFN lin1 + ReLU
    gemm_tf32_async<1><<<dim3(Fn / TBN, BQ / 64), 256, smem1>>>(x2, lin1_w, lin1_b, ff, BQ, Fn, Dn, 1);
    // 11. FFN lin2
    gemm_tf32_async<1><<<dim3(Dn / TBN, BQ / 64), 256, smem1>>>(ff, lin2_w, lin2_b, tmp, BQ, Dn, Fn, 0);
    // 12. out = LN(x2 + ffn)
    add_ln_kernel<<<BQ, Dn>>>(x2, tmp, norm3_g, norm3_b, out);
}